// round 1
// baseline (speedup 1.0000x reference)
#include <cuda_runtime.h>
#include <math.h>

// ---------------- Problem constants ----------------
#define BB   128     // batch
#define LL   128     // seq (events)
#define JJ   64      // bag size
#define EE   128     // embed dim
#define SS   129     // L+1 tokens
#define HH   2       // heads
#define HD   64      // head dim
#define CATN 1000
#define ROWS (BB*SS) // 16512

// ---------------- Device scratch (static, allocation-free) ----------------
__device__ float g_x  [ROWS*EE];
__device__ float g_q  [ROWS*EE];
__device__ float g_k  [ROWS*EE];
__device__ float g_v  [ROWS*EE];
__device__ float g_o  [ROWS*EE];
__device__ float g_tmp[ROWS*EE];
__device__ float g_f1 [ROWS*EE];
__device__ float g_f2 [ROWS*EE];
__device__ float g_P  [BB*HH*SS*SS];   // attention probs
__device__ float g_h  [BB*EE];
__device__ float g_x1 [BB*CATN];

// ---------------- Embedding: masked bag-sum over J + dt ----------------
__global__ void embed_kernel(const int* __restrict__ cat_arr,
                             const int* __restrict__ amt_arr,
                             const int* __restrict__ dt_arr,
                             const float* __restrict__ cat_tab,
                             const float* __restrict__ amt_tab,
                             const float* __restrict__ dt_tab)
{
    int bl = blockIdx.x;          // b*L + l
    int e  = threadIdx.x;         // 0..127
    __shared__ int sc[JJ];
    __shared__ int sa[JJ];
    if (e < JJ) {
        sc[e] = cat_arr[(size_t)bl*JJ + e];
        sa[e] = amt_arr[(size_t)bl*JJ + e];
    }
    __syncthreads();
    float acc = 0.f;
    #pragma unroll 4
    for (int j = 0; j < JJ; j++) {
        int c = sc[j];
        if (c != CATN) {  // uniform branch across warp
            acc += cat_tab[(size_t)c*EE + e];
            acc += amt_tab[(size_t)sa[j]*EE + e];
        }
    }
    acc += dt_tab[(size_t)dt_arr[bl]*EE + e];
    int b = bl >> 7, l = bl & 127;
    g_x[((size_t)b*SS + l + 1)*EE + e] = acc;
}

__global__ void id_kernel(const int* __restrict__ id_arr,
                          const float* __restrict__ id_tab)
{
    int b = blockIdx.x, e = threadIdx.x;
    g_x[(size_t)b*SS*EE + e] = id_tab[(size_t)id_arr[b]*EE + e];
}

// ---------------- Generic tiled SGEMM: C = A[MxK] @ W[KxN] + bias (opt relu) ---
__global__ void sgemm(const float* __restrict__ A, const float* __restrict__ W,
                      const float* __restrict__ bias, float* __restrict__ C,
                      int M, int N, int K, int relu)
{
    __shared__ float sA[16][64];
    __shared__ float sB[16][68];
    int bm = blockIdx.y * 64, bn = blockIdx.x * 64;
    int tid = threadIdx.x;
    int tx = tid & 15, ty = tid >> 4;
    float acc[4][4] = {};
    for (int k0 = 0; k0 < K; k0 += 16) {
        // A tile: 64 rows x 16 cols
        int ar = tid >> 2, ac0 = (tid & 3) * 4;
        #pragma unroll
        for (int i = 0; i < 4; i++) {
            int m = bm + ar, k = k0 + ac0 + i;
            sA[ac0 + i][ar] = (m < M && k < K) ? A[(size_t)m*K + k] : 0.f;
        }
        // W tile: 16 rows x 64 cols
        int bc = tid & 63, br0 = tid >> 6;
        #pragma unroll
        for (int i = 0; i < 4; i++) {
            int k = k0 + br0 + i*4, n = bn + bc;
            sB[br0 + i*4][bc] = (k < K && n < N) ? W[(size_t)k*N + n] : 0.f;
        }
        __syncthreads();
        #pragma unroll
        for (int k = 0; k < 16; k++) {
            float a[4], b[4];
            #pragma unroll
            for (int i = 0; i < 4; i++) a[i] = sA[k][ty*4 + i];
            #pragma unroll
            for (int j = 0; j < 4; j++) b[j] = sB[k][tx*4 + j];
            #pragma unroll
            for (int i = 0; i < 4; i++)
                #pragma unroll
                for (int j = 0; j < 4; j++)
                    acc[i][j] += a[i] * b[j];
        }
        __syncthreads();
    }
    #pragma unroll
    for (int i = 0; i < 4; i++) {
        int m = bm + ty*4 + i;
        if (m >= M) continue;
        #pragma unroll
        for (int j = 0; j < 4; j++) {
            int n = bn + tx*4 + j;
            if (n >= N) continue;
            float vv = acc[i][j] + bias[n];
            if (relu) vv = fmaxf(vv, 0.f);
            C[(size_t)m*N + n] = vv;
        }
    }
}

// ---------------- Attention: scores + softmax (warp per query row) ----------
__global__ void attn_scores(const float* __restrict__ q,
                            const float* __restrict__ k,
                            float* __restrict__ P)
{
    int bh = blockIdx.x;
    int b = bh >> 1, h = bh & 1;
    __shared__ float sk[SS*65];    // pitch 65: conflict-free row-strided reads
    __shared__ float sq[8][64];
    int tid = threadIdx.x;         // 256 threads
    for (int idx = tid; idx < SS*HD; idx += 256) {
        int s = idx >> 6, d = idx & 63;
        sk[s*65 + d] = k[((size_t)b*SS + s)*EE + h*HD + d];
    }
    __syncthreads();
    int wid = tid >> 5, lane = tid & 31;
    for (int it = 0; it < 17; it++) {
        int i = it*8 + wid;
        __syncwarp();
        if (i < SS) {
            const float* qr = q + ((size_t)b*SS + i)*EE + h*HD;
            sq[wid][lane]      = qr[lane];
            sq[wid][lane + 32] = qr[lane + 32];
        }
        __syncwarp();
        if (i < SS) {
            float sc[5];
            float mx = -1e30f;
            #pragma unroll
            for (int m = 0; m < 5; m++) {
                int j = lane + m*32;
                float s = -1e30f;
                if (j < SS) {
                    s = 0.f;
                    #pragma unroll 8
                    for (int d = 0; d < HD; d++) s += sq[wid][d] * sk[j*65 + d];
                    s *= 0.125f;   // 1/sqrt(64)
                }
                sc[m] = s;
                mx = fmaxf(mx, s);
            }
            #pragma unroll
            for (int o = 16; o > 0; o >>= 1)
                mx = fmaxf(mx, __shfl_xor_sync(0xffffffffu, mx, o));
            float sum = 0.f;
            #pragma unroll
            for (int m = 0; m < 5; m++) {
                int j = lane + m*32;
                if (j < SS) { sc[m] = __expf(sc[m] - mx); sum += sc[m]; }
            }
            #pragma unroll
            for (int o = 16; o > 0; o >>= 1)
                sum += __shfl_xor_sync(0xffffffffu, sum, o);
            float inv = 1.f / sum;
            #pragma unroll
            for (int m = 0; m < 5; m++) {
                int j = lane + m*32;
                if (j < SS) P[((size_t)bh*SS + i)*SS + j] = sc[m] * inv;
            }
        }
    }
}

// ---------------- Attention: out = P @ V (warp per query row) ---------------
__global__ void attn_av(const float* __restrict__ P,
                        const float* __restrict__ v,
                        float* __restrict__ o)
{
    int bh = blockIdx.x;
    int b = bh >> 1, h = bh & 1;
    __shared__ float sv[SS*64];
    __shared__ float sp[8][132];
    int tid = threadIdx.x;   // 256
    for (int idx = tid; idx < SS*HD; idx += 256) {
        int s = idx >> 6, d = idx & 63;
        sv[idx] = v[((size_t)b*SS + s)*EE + h*HD + d];
    }
    __syncthreads();
    int wid = tid >> 5, lane = tid & 31;
    for (int it = 0; it < 17; it++) {
        int i = it*8 + wid;
        __syncwarp();
        if (i < SS) {
            #pragma unroll
            for (int m = 0; m < 5; m++) {
                int j = lane + m*32;
                if (j < SS) sp[wid][j] = P[((size_t)bh*SS + i)*SS + j];
            }
        }
        __syncwarp();
        if (i < SS) {
            float a0 = 0.f, a1 = 0.f;
            #pragma unroll 4
            for (int j = 0; j < SS; j++) {
                float p = sp[wid][j];
                a0 += p * sv[j*64 + lane];
                a1 += p * sv[j*64 + lane + 32];
            }
            float* orow = o + ((size_t)b*SS + i)*EE + h*HD;
            orow[lane]      = a0;
            orow[lane + 32] = a1;
        }
    }
}

// ---------------- LayerNorm(x + add) in place ----------------
__global__ void ln_add(float* __restrict__ x, const float* __restrict__ add,
                       const float* __restrict__ g, const float* __restrict__ bta)
{
    int r = blockIdx.x, e = threadIdx.x;   // 128 threads
    __shared__ float red[4];
    float v = x[(size_t)r*EE + e] + add[(size_t)r*EE + e];
    float s = v;
    #pragma unroll
    for (int o = 16; o > 0; o >>= 1) s += __shfl_xor_sync(0xffffffffu, s, o);
    if ((e & 31) == 0) red[e >> 5] = s;
    __syncthreads();
    float mu = (red[0] + red[1] + red[2] + red[3]) * (1.f/128.f);
    __syncthreads();
    float d = v - mu;
    float s2 = d * d;
    #pragma unroll
    for (int o = 16; o > 0; o >>= 1) s2 += __shfl_xor_sync(0xffffffffu, s2, o);
    if ((e & 31) == 0) red[e >> 5] = s2;
    __syncthreads();
    float var = (red[0] + red[1] + red[2] + red[3]) * (1.f/128.f);
    x[(size_t)r*EE + e] = d * rsqrtf(var + 1e-5f) * g[e] + bta[e];
}

// ---------------- Mean pool over tokens 1..128 ----------------
__global__ void pool_kernel(const float* __restrict__ x, float* __restrict__ h)
{
    int b = blockIdx.x, e = threadIdx.x;
    float s = 0.f;
    #pragma unroll 4
    for (int l = 1; l <= LL; l++) s += x[((size_t)b*SS + l)*EE + e];
    h[(size_t)b*EE + e] = s * (1.f/128.f);
}

// ---------------- Launch ----------------
extern "C" void kernel_launch(void* const* d_in, const int* in_sizes, int n_in,
                              void* d_out, int out_size)
{
    (void)in_sizes; (void)n_in; (void)out_size;
    const int*   cat_arr = (const int*)  d_in[0];
    const int*   dt_arr  = (const int*)  d_in[1];
    const int*   amt_arr = (const int*)  d_in[2];
    const int*   id_arr  = (const int*)  d_in[3];
    const float* id_tab  = (const float*)d_in[4];
    const float* cat_tab = (const float*)d_in[5];
    const float* amt_tab = (const float*)d_in[6];
    const float* dt_tab  = (const float*)d_in[7];
    const float* Wq = (const float*)d_in[8],  *bq = (const float*)d_in[9];
    const float* Wk = (const float*)d_in[10], *bk = (const float*)d_in[11];
    const float* Wv = (const float*)d_in[12], *bv = (const float*)d_in[13];
    const float* Wo = (const float*)d_in[14], *bo = (const float*)d_in[15];
    const float* ln1g = (const float*)d_in[16], *ln1b = (const float*)d_in[17];
    const float* W1 = (const float*)d_in[18], *b1 = (const float*)d_in[19];
    const float* W2 = (const float*)d_in[20], *b2 = (const float*)d_in[21];
    const float* ln2g = (const float*)d_in[22], *ln2b = (const float*)d_in[23];
    const float* l1W = (const float*)d_in[24], *l1b = (const float*)d_in[25];
    const float* l2W = (const float*)d_in[26], *l2b = (const float*)d_in[27];
    float* out = (float*)d_out;

    float *x, *q, *k, *v, *o, *tmp, *f1, *f2, *P, *h, *x1;
    cudaGetSymbolAddress((void**)&x,   g_x);
    cudaGetSymbolAddress((void**)&q,   g_q);
    cudaGetSymbolAddress((void**)&k,   g_k);
    cudaGetSymbolAddress((void**)&v,   g_v);
    cudaGetSymbolAddress((void**)&o,   g_o);
    cudaGetSymbolAddress((void**)&tmp, g_tmp);
    cudaGetSymbolAddress((void**)&f1,  g_f1);
    cudaGetSymbolAddress((void**)&f2,  g_f2);
    cudaGetSymbolAddress((void**)&P,   g_P);
    cudaGetSymbolAddress((void**)&h,   g_h);
    cudaGetSymbolAddress((void**)&x1,  g_x1);

    // 1. embeddings
    embed_kernel<<<BB*LL, EE>>>(cat_arr, amt_arr, dt_arr, cat_tab, amt_tab, dt_tab);
    id_kernel<<<BB, EE>>>(id_arr, id_tab);

    // 2. QKV projections
    dim3 gEE(2, ROWS/64);              // N=128 -> 2, M=16512 -> 258
    sgemm<<<gEE, 256>>>(x, Wq, bq, q, ROWS, EE, EE, 0);
    sgemm<<<gEE, 256>>>(x, Wk, bk, k, ROWS, EE, EE, 0);
    sgemm<<<gEE, 256>>>(x, Wv, bv, v, ROWS, EE, EE, 0);

    // 3. attention
    attn_scores<<<BB*HH, 256>>>(q, k, P);
    attn_av<<<BB*HH, 256>>>(P, v, o);

    // 4. out proj + residual + LN1
    sgemm<<<gEE, 256>>>(o, Wo, bo, tmp, ROWS, EE, EE, 0);
    ln_add<<<ROWS, EE>>>(x, tmp, ln1g, ln1b);

    // 5. FFN + residual + LN2
    sgemm<<<gEE, 256>>>(x, W1, b1, f1, ROWS, EE, EE, 1);
    sgemm<<<gEE, 256>>>(f1, W2, b2, f2, ROWS, EE, EE, 0);
    ln_add<<<ROWS, EE>>>(x, f2, ln2g, ln2b);

    // 6. pool + classifier head
    pool_kernel<<<BB, EE>>>(x, h);
    dim3 gL1((CATN + 63)/64, 2);       // N=1000 -> 16, M=128 -> 2
    sgemm<<<gL1, 256>>>(h,  l1W, l1b, x1,  BB, CATN, EE,   1);
    sgemm<<<gL1, 256>>>(x1, l2W, l2b, out, BB, CATN, CATN, 0);
}